// round 15
// baseline (speedup 1.0000x reference)
#include <cuda_runtime.h>

#define HH 1024
#define WW 1024
#define RC 19                  // cone radius = n_steps-1
#define REG 39                 // 2*RC+1
#define PITCH 48               // smem row width (floats)
#define SROWS 41               // REG + 2 halo rows (rows 0 and 40 stay zero)
#define NSIM 416               // 13 warps
#define FILLB 512

#define PDL_TRIGGER() asm volatile("griddepcontrol.launch_dependents;")

// band[w]: urgency-ordered bands assigned to high warp-ids first
// (hi-wid-first arbiter => central bands' MUFU bursts get priority)
__constant__ int c_band[13] = {12, 0, 11, 1, 10, 2, 9, 3, 8, 4, 7, 5, 6};

// ---------------------------------------------------------------------------
// K1: light-cone sim; each warp computes its own band's coefficients in the
// preamble (fast-math), then runs 19 steps with progressive barrier joins.
// Arrival telescoped: arr = N - sum_{t=1}^{N-1} s_t.
// ---------------------------------------------------------------------------
__global__ void __launch_bounds__(NSIM, 1)
sim_kernel(const float* __restrict__ height,
           const float* __restrict__ age,
           const float* __restrict__ moisture,
           const float* __restrict__ la, const float* __restrict__ lb,
           const float* __restrict__ lg, const float* __restrict__ ld,
           const float* __restrict__ ws, const float* __restrict__ wd,
           const float* __restrict__ ignv,
           const int*   __restrict__ ip,
           const int*   __restrict__ nsp,
           const int*   __restrict__ nssp,
           float*       __restrict__ out) {
    PDL_TRIGGER();   // release the concurrent fill immediately

    __shared__ float sbuf[2][SROWS * PITCH];

    int tid = threadIdx.x;
    for (int i = tid; i < (2 * SROWS * PITCH) / 4; i += NSIM)
        ((float4*)sbuf)[i] = make_float4(0.f, 0.f, 0.f, 0.f);

    // scalar inputs: one parallel DRAM round at the chain head
    int ns  = nsp[0];
    int nss = nssp[0];
    float ig  = ignv[0];
    float fns = (float)ns;
    int or0 = ip[0] - RC;
    int oc0 = ip[1] - RC;
    float alpha = __expf(la[0]);
    float beta  = __expf(lb[0]);
    float gamma = __expf(lg[0]);
    float delta = __expf(ld[0]);

    int w    = tid >> 5;
    int lane = tid & 31;
    int band = c_band[w];
    int lrow = lane / 10;              // 0,1,2 workers; 3 = idle (lanes 30,31)
    int g    = lane - lrow * 10;
    bool worker = (lrow < 3);
    int row = worker ? (band * 3 + lrow) : 0;   // region row 0..38
    int c0  = g * 4;

    int rbase = row * PITCH + c0;
    int widx  = (worker ? (row + 1) : 40) * PITCH + c0 + 4;

    int a3 = 3 * band;
    int wmin = (RC >= a3 && RC <= a3 + 2) ? 0
             : ((a3 > RC) ? (a3 - RC) : (RC - (a3 + 2)));
    int jw = (wmin > 1) ? (wmin - 1) : 1;   // barrier-join step

    __syncthreads();                         // smem zeros visible
    if (tid == 0) sbuf[0][(RC + 1) * PITCH + (RC + 4)] = ig;   // state_0
    __syncthreads();

    // ---- per-warp coefficient computation (own band only, fast-math) ------
    float cf[8][4], gn[4], cur[4], acc[4];
    #pragma unroll
    for (int i = 0; i < 4; i++) {
        gn[i] = 0.f; cur[i] = 0.f; acc[i] = 0.f;
        #pragma unroll
        for (int k = 0; k < 8; k++) cf[k][i] = 0.f;
    }
    if (worker) {
        const float distk[8] = {0.83f, 1.f, 0.83f, 1.f, 1.f, 0.83f, 1.f, 0.83f};
        const float uik[8]   = {-0.70710678f, -1.f, -0.70710678f, 0.f, 0.f,
                                 0.70710678f,  1.f,  0.70710678f};
        const float ujk[8]   = {-0.70710678f,  0.f,  0.70710678f, -1.f, 1.f,
                                -0.70710678f,  0.f,  0.70710678f};
        const int   kdj[8]   = {-1, 0, 1, -1, 1, -1, 0, 1};

        int gi  = or0 + row;
        int gj0 = oc0 + c0;

        // mid row (dr=1): heights + wind at window cols c0-1..c0+4
        float hm[6], wym[6], wxm[6];
        bool  pvm[6];
        bool rvm = (gi >= 0) && (gi < HH);
        #pragma unroll
        for (int dc = 0; dc < 6; dc++) {
            int gc = gj0 - 1 + dc;
            bool v = rvm && (gc >= 0) && (gc < WW);
            pvm[dc] = v;
            int o = (v ? gi : 0) * WW + (v ? gc : 0);
            float hh = v ? height[o] : 0.f;
            float s  = v ? ws[o] : 0.f;
            float d  = v ? wd[o] : 0.f;
            hm[dc]  = hh;
            wym[dc] = s * __cosf(d);
            wxm[dc] = s * __sinf(d);
        }
        bool cellv[4];
        #pragma unroll
        for (int i = 0; i < 4; i++) cellv[i] = (c0 + i < REG) && pvm[i + 1];

        // gain (4 cells)
        #pragma unroll
        for (int i = 0; i < 4; i++) {
            if (cellv[i]) {
                int o = gi * WW + gj0 + i;
                float a = age[o];
                float m = moisture[o];
                float ratio = fmaxf(a * (1.0f / 30.0f), 1e-6f);    // T_MAX = 30
                float below = exp2f(__powf(ratio, alpha)) - 1.0f;  // (1+P)^(r^a)-1
                float af = (a < 30.0f) ? below : 1.0f;
                gn[i] = af * __expf(-beta * m);
            }
        }

        // mid-row neighbors: k=3 (dj=-1), k=4 (dj=+1)
        #pragma unroll
        for (int kk = 3; kk <= 4; kk++) {
            #pragma unroll
            for (int i = 0; i < 4; i++) {
                int dc = i + 1 + kdj[kk];
                bool mask = cellv[i] && pvm[dc];
                float dh = hm[i + 1] - hm[dc];
                float phi = (dh <= 0.f) ? __expf(gamma * dh)
                                        : fmaf(gamma, sqrtf(dh), 1.f);
                float align = uik[kk] * wym[dc] + ujk[kk] * wxm[dc];
                float wf = fminf(__expf(delta * align), 2.0f);
                cf[kk][i] = mask ? distk[kk] * wf * phi : 0.f;
            }
        }
        // top row (dr=0 -> k 0..2) and bottom row (dr=2 -> k 5..7), streamed
        #pragma unroll
        for (int half = 0; half < 2; half++) {
            int gr = gi - 1 + 2 * half;             // gi-1 or gi+1
            int k0 = half ? 5 : 0;
            bool rv = (gr >= 0) && (gr < HH);
            float hr[6], wyr[6], wxr[6];
            bool  pvr[6];
            #pragma unroll
            for (int dc = 0; dc < 6; dc++) {
                int gc = gj0 - 1 + dc;
                bool v = rv && (gc >= 0) && (gc < WW);
                pvr[dc] = v;
                int o = (v ? gr : 0) * WW + (v ? gc : 0);
                float hh = v ? height[o] : 0.f;
                float s  = v ? ws[o] : 0.f;
                float d  = v ? wd[o] : 0.f;
                hr[dc]  = hh;
                wyr[dc] = s * __cosf(d);
                wxr[dc] = s * __sinf(d);
            }
            #pragma unroll
            for (int kk = 0; kk < 3; kk++) {
                int k = k0 + kk;
                #pragma unroll
                for (int i = 0; i < 4; i++) {
                    int dc = i + 1 + kdj[k];
                    bool mask = cellv[i] && pvr[dc];
                    float dh = hm[i + 1] - hr[dc];
                    float phi = (dh <= 0.f) ? __expf(gamma * dh)
                                            : fmaf(gamma, sqrtf(dh), 1.f);
                    float align = uik[k] * wyr[dc] + ujk[k] * wxr[dc];
                    float wf = fminf(__expf(delta * align), 2.0f);
                    cf[k][i] = mask ? distk[k] * wf * phi : 0.f;
                }
            }
        }
    }
    // ignition cell (RC,RC): band 6, lrow 1, g 4, slot 3 (register-resident)
    if (band == 6 && lrow == 1 && g == 4) cur[3] = ig;

    // step body: read state_{t-1} from sbuf[(t-1)&1], write state_t to sbuf[t&1]
    auto body = [&](int t) {
        const float* rb = sbuf[(t - 1) & 1] + rbase;
        float  uA = rb[3];
        float4 uv = *(const float4*)(rb + 4);
        float  uB = rb[8];
        float  mA = rb[PITCH + 3];
        float4 mv = *(const float4*)(rb + PITCH + 4);
        float  mB = rb[PITCH + 8];
        float  dA = rb[2 * PITCH + 3];
        float4 dv = *(const float4*)(rb + 2 * PITCH + 4);
        float  dB = rb[2 * PITCH + 8];

        float up[6] = {uA, uv.x, uv.y, uv.z, uv.w, uB};
        float mi[6] = {mA, mv.x, mv.y, mv.z, mv.w, mB};
        float dn[6] = {dA, dv.x, dv.y, dv.z, dv.w, dB};
        #pragma unroll
        for (int i = 0; i < 4; i++) {
            float ta = cf[0][i] * up[i] + cf[1][i] * up[i + 1];
            ta = fmaf(cf[2][i], up[i + 2], ta);
            ta = fmaf(cf[3][i], mi[i], ta);
            float tb = cf[4][i] * mi[i + 2] + cf[5][i] * dn[i];
            tb = fmaf(cf[6][i], dn[i + 1], tb);
            tb = fmaf(cf[7][i], dn[i + 2], tb);
            cur[i] = fminf(fmaf(gn[i], ta + tb, cur[i]), 1.0f);  // state >= 0
            acc[i] += cur[i];                                    // telescoped
        }
        *(float4*)(sbuf[t & 1] + widx) =
            make_float4(cur[0], cur[1], cur[2], cur[3]);
    };

    if (ns == 20 && nss == 1) {
        // ---- fast path: t=1..18 with progressive barrier subsets, then t=19
        #pragma unroll
        for (int t = 1; t <= 18; t++) {
            const int seg = (t - 1) / 3;              // 0..5
            const int cnt = 32 * (3 + 2 * seg);       // 96..416
            if (t >= jw) {
                if (t >= wmin) body(t);
                if (cnt >= NSIM) {
                    __syncthreads();
                } else {
                    asm volatile("bar.sync %0, %1;"
                                 :: "r"(seg + 1), "r"(cnt) : "memory");
                }
            }
        }
        body(19);   // final step: everyone; no trailing barrier needed
    } else {
        // ---- generic path: full-block barriers every substep ----
        int cb = 0;
        for (int t = 1; t < ns; t++) {
            bool wact = (t * nss >= wmin);
            for (int s = 0; s < nss; s++) {
                if (wact) {
                    const float* rb = sbuf[cb] + rbase;
                    float  uA = rb[3];
                    float4 uv = *(const float4*)(rb + 4);
                    float  uB = rb[8];
                    float  mA = rb[PITCH + 3];
                    float4 mv = *(const float4*)(rb + PITCH + 4);
                    float  mB = rb[PITCH + 8];
                    float  dA = rb[2 * PITCH + 3];
                    float4 dv = *(const float4*)(rb + 2 * PITCH + 4);
                    float  dB = rb[2 * PITCH + 8];
                    float up[6] = {uA, uv.x, uv.y, uv.z, uv.w, uB};
                    float mi[6] = {mA, mv.x, mv.y, mv.z, mv.w, mB};
                    float dn[6] = {dA, dv.x, dv.y, dv.z, dv.w, dB};
                    #pragma unroll
                    for (int i = 0; i < 4; i++) {
                        float ta = cf[0][i] * up[i] + cf[1][i] * up[i + 1];
                        ta = fmaf(cf[2][i], up[i + 2], ta);
                        ta = fmaf(cf[3][i], mi[i], ta);
                        float tb = cf[4][i] * mi[i + 2] + cf[5][i] * dn[i];
                        tb = fmaf(cf[6][i], dn[i + 1], tb);
                        tb = fmaf(cf[7][i], dn[i + 2], tb);
                        cur[i] = fminf(fmaf(gn[i], ta + tb, cur[i]), 1.0f);
                    }
                    *(float4*)(sbuf[cb ^ 1] + widx) =
                        make_float4(cur[0], cur[1], cur[2], cur[3]);
                }
                __syncthreads();
                cb ^= 1;
            }
            if (wact) {
                #pragma unroll
                for (int i = 0; i < 4; i++) acc[i] += cur[i];
            }
        }
    }

    if (worker) {
        int gi = or0 + row;
        if (gi >= 0 && gi < HH) {
            #pragma unroll
            for (int i = 0; i < 4; i++) {
                int gj = oc0 + c0 + i;
                if ((c0 + i < REG) && gj >= 0 && gj < WW)
                    out[gi * WW + gj] = fns - acc[i];
            }
        }
    }
}

// ---------------------------------------------------------------------------
// K2: fill arrival = n_steps everywhere EXCEPT the 39x39 cone region (which
// the sim kernel writes) -> disjoint from sim, runs concurrently via PDL.
// ---------------------------------------------------------------------------
__global__ void __launch_bounds__(256)
fill_kernel(float4* __restrict__ out4,
            const int* __restrict__ ip,
            const int* __restrict__ nsp) {
    int or0 = ip[0] - RC;
    int oc0 = ip[1] - RC;
    float v = (float)(*nsp);
    float4 f = make_float4(v, v, v, v);
    float* out = (float*)out4;
    int base = blockIdx.x * 256 + threadIdx.x;
    #pragma unroll
    for (int g = 0; g < 2; g++) {
        int fi = base + g * (FILLB * 256);
        int row = fi >> 8;                 // 256 float4 per row
        int col = (fi & 255) << 2;
        bool rowin = (row >= or0) && (row < or0 + REG);
        bool colov = (col + 3 >= oc0) && (col <= oc0 + REG - 1);
        if (!(rowin && colov)) {
            out4[fi] = f;
        } else {
            #pragma unroll
            for (int e = 0; e < 4; e++) {
                int cc = col + e;
                if (cc < oc0 || cc >= oc0 + REG)
                    out[row * WW + cc] = v;
            }
        }
    }
}

// ---------------------------------------------------------------------------
extern "C" void kernel_launch(void* const* d_in, const int* in_sizes, int n_in,
                              void* d_out, int out_size) {
    const float* height   = (const float*)d_in[0];
    const float* age      = (const float*)d_in[1];
    const float* moisture = (const float*)d_in[2];
    const float* la       = (const float*)d_in[3];
    const float* lb       = (const float*)d_in[4];
    const float* lg       = (const float*)d_in[5];
    const float* ld       = (const float*)d_in[6];
    const float* ws       = (const float*)d_in[7];
    const float* wd       = (const float*)d_in[8];
    const float* ignv     = (const float*)d_in[9];
    const int*   ip       = (const int*)d_in[10];
    const int*   ns       = (const int*)d_in[11];
    const int*   nss      = (const int*)d_in[12];
    float* out = (float*)d_out;

    // K1: self-sufficient sim (per-warp coefs, no coef kernel, no PDL wait)
    sim_kernel<<<1, NSIM>>>(height, age, moisture, la, lb, lg, ld, ws, wd,
                            ignv, ip, ns, nss, out);

    // K2: cone-excluded fill — released by sim's entry trigger, concurrent
    cudaLaunchAttribute attr[1];
    attr[0].id = cudaLaunchAttributeProgrammaticStreamSerialization;
    attr[0].val.programmaticStreamSerializationAllowed = 1;
    cudaLaunchConfig_t cfg = {};
    cfg.gridDim  = dim3(FILLB, 1, 1);
    cfg.blockDim = dim3(256, 1, 1);
    cfg.attrs = attr;
    cfg.numAttrs = 1;
    cudaLaunchKernelEx(&cfg, fill_kernel, (float4*)out, ip, ns);
}